// round 2
// baseline (speedup 1.0000x reference)
#include <cuda_runtime.h>

#define N_EDGES 250000
#define N_NODES 10000
#define N_RBF   10
#define FEAT    144
#define P_TOTAL 4864
#define TILE_E  32
#define THREADS 128
#define RT_PAD  17              // padded v-row stride (conflict-free, 17 coprime 32)
#define RT_RSTRIDE (16 * RT_PAD) // 272 floats per r-slice

__constant__ float cg_c[1225];

// ---------------------------------------------------------------------------
// Per-path fully-unrolled worker, 4 edges per lane.
//   lane m = lane&15 is the mul index (v for tmp phase, w for apply phase),
//   eh = lane>>4 selects which 4-edge group of the warp's 8 edges.
// tmp[v][o] lives in lane v's registers, fetched via shfl(width=16).
// Rt is [r][v*17 + w] so the lane=w read is a conflict-free broadcast that
// feeds 4 edges' W accumulation per LDS.
// ---------------------------------------------------------------------------
template<int IO, int II, int LF, int CGOFF>
__device__ __forceinline__ void do_path(
    const float* __restrict__ F_s,    // [TILE_E][FEAT]
    const float* __restrict__ Ys_s,   // [TILE_E][25]
    const float* __restrict__ Rt,     // [10][272] transposed+padded
    const float (&rad)[4][N_RBF],
    int m, int l0,
    float (&outv)[4][5])
{
    constexpr int DOUT = 2 * IO + 1;
    constexpr int DI   = 2 * II + 1;
    constexpr int DF   = 2 * LF + 1;
    constexpr int FOFF = (II == 0) ? 0 : ((II == 1) ? 16 : 64);
    constexpr int YOFF = LF * LF;
    const float NORM =
        (DF == 1) ? 1.0f :
        (DF == 3) ? 0.57735026918962576f :
        (DF == 5) ? 0.44721359549995794f :
        (DF == 7) ? 0.37796447300922723f :
                    0.33333333333333333f;

    // ---- tmp[v=m][o] for this lane's 4 edges ----
    float tA[4][DOUT];
    {
        float FA[4][DI];
#pragma unroll
        for (int j = 0; j < 4; j++)
#pragma unroll
            for (int i = 0; i < DI; i++)
                FA[j][i] = F_s[(l0 + j) * FEAT + FOFF + m * DI + i];

#pragma unroll
        for (int j = 0; j < 4; j++)
#pragma unroll
            for (int o = 0; o < DOUT; o++) tA[j][o] = 0.f;

#pragma unroll
        for (int f = 0; f < DF; f++) {
            float y[4];
#pragma unroll
            for (int j = 0; j < 4; j++)
                y[j] = Ys_s[(l0 + j) * 25 + YOFF + f];
#pragma unroll
            for (int o = 0; o < DOUT; o++) {
                float g[4] = {0.f, 0.f, 0.f, 0.f};
#pragma unroll
                for (int i = 0; i < DI; i++) {
                    float c = cg_c[CGOFF + (o * DI + i) * DF + f];  // LDCU (uniform)
#pragma unroll
                    for (int j = 0; j < 4; j++) g[j] += FA[j][i] * c;
                }
#pragma unroll
                for (int j = 0; j < 4; j++) tA[j][o] += y[j] * g[j];
            }
        }
#pragma unroll
        for (int j = 0; j < 4; j++)
#pragma unroll
            for (int o = 0; o < DOUT; o++) tA[j][o] *= NORM;
    }

    // ---- W[w=m][v] on the fly (4 edges share each Rt read) + apply via shfl ----
#pragma unroll
    for (int v = 0; v < 16; v++) {
        float w[4] = {0.f, 0.f, 0.f, 0.f};
#pragma unroll
        for (int r = 0; r < N_RBF; r++) {
            float rv = Rt[r * RT_RSTRIDE + v * RT_PAD + m];  // 1 LDS -> 4 FMA
#pragma unroll
            for (int j = 0; j < 4; j++) w[j] += rad[j][r] * rv;
        }
#pragma unroll
        for (int o = 0; o < DOUT; o++) {
#pragma unroll
            for (int j = 0; j < 4; j++) {
                float tv = __shfl_sync(0xffffffffu, tA[j][o], v, 16);
                outv[j][o] += w[j] * tv;
            }
        }
    }
}

// ---------------------------------------------------------------------------
__global__ void __launch_bounds__(THREADS)
conv_kernel(const float* __restrict__ features,
            const float* __restrict__ R,
            const float* __restrict__ Ys,
            const float* __restrict__ radii,
            const float* __restrict__ n_norm,
            const int*   __restrict__ map_a,
            const int*   __restrict__ map_b,
            float* __restrict__ out)
{
    __shared__ float Rt[N_RBF * RT_RSTRIDE];   // 2720 floats, padded transposed
    __shared__ float F_s[TILE_E * FEAT];
    __shared__ float Ys_s[TILE_E * 25];

    const int tid  = threadIdx.x;
    const int warp = tid >> 5;
    const int lane = tid & 31;
    const int m    = lane & 15;
    const int eh   = lane >> 4;
    const int e0   = blockIdx.x * TILE_E;
    const int l0   = warp * 8 + eh * 4;        // this lane's first local edge

    // ---- stage gathered features (float4) and Ys ----
    {
        const int NV = TILE_E * FEAT / 4;      // 1152
        for (int idx = tid; idx < NV; idx += THREADS) {
            int le = idx / (FEAT / 4), c4 = idx - le * (FEAT / 4);
            int e  = e0 + le;
            int b  = (e < N_EDGES) ? map_b[e] : 0;
            ((float4*)F_s)[idx] =
                ((const float4*)(features + (size_t)b * FEAT))[c4];
        }
    }
    for (int idx = tid; idx < TILE_E * 25; idx += THREADS) {
        int le = idx / 25, c = idx - le * 25;
        int e  = e0 + le;
        Ys_s[idx] = (e < N_EDGES) ? Ys[(size_t)e * 25 + c] : 0.f;
    }
    // visibility of F_s/Ys_s is covered by the first STAGE_R's post-sync.

    // ---- per-lane edge bindings (4 edges) ----
    bool  vj[4];
    int   aj[4];
    float nn[4];
    float rad[4][N_RBF];
#pragma unroll
    for (int j = 0; j < 4; j++) {
        int e  = e0 + l0 + j;
        vj[j]  = (e < N_EDGES);
        int ee = vj[j] ? e : 0;
#pragma unroll
        for (int r = 0; r < N_RBF; r++)
            rad[j][r] = vj[j] ? radii[(size_t)ee * N_RBF + r] : 0.f;
        aj[j] = map_a[ee];
        nn[j] = vj[j] ? n_norm[aj[j]] : 0.f;
    }

    float outv[4][5];
#pragma unroll
    for (int j = 0; j < 4; j++)
#pragma unroll
        for (int o = 0; o < 5; o++) outv[j][o] = 0.f;

#define STAGE_R(P)                                                             \
    do {                                                                       \
        __syncthreads();                                                       \
        for (int idx = tid; idx < N_RBF * 256; idx += THREADS) {               \
            int r = idx >> 8, c = idx & 255;  /* c = w*16 + v */               \
            Rt[r * RT_RSTRIDE + (c & 15) * RT_PAD + (c >> 4)] =                \
                R[(size_t)r * P_TOTAL + (P) * 256 + c];                        \
        }                                                                      \
        __syncthreads();                                                       \
    } while (0)

#define RUN(P, IO, II, LF, CGOFF)                                              \
    do {                                                                       \
        STAGE_R(P);                                                            \
        do_path<IO, II, LF, CGOFF>(F_s, Ys_s, Rt, rad, m, l0, outv);           \
    } while (0)

    // ---------------- io = 0 (DOUT = 1, out offset 0) -----------------------
    RUN(0, 0, 0, 0, 0);
    RUN(1, 0, 1, 1, 1);
    RUN(2, 0, 2, 2, 10);
#pragma unroll
    for (int j = 0; j < 4; j++)
        if (vj[j]) atomicAdd(&out[(size_t)aj[j] * FEAT + m], nn[j] * outv[j][0]);
#pragma unroll
    for (int j = 0; j < 4; j++)
#pragma unroll
        for (int o = 0; o < 5; o++) outv[j][o] = 0.f;

    // ---------------- io = 1 (DOUT = 3, out offset 16) ----------------------
    RUN(3, 1, 0, 1, 35);
    RUN(4, 1, 1, 0, 44);
    RUN(5, 1, 1, 1, 53);
    RUN(6, 1, 1, 2, 80);
    RUN(7, 1, 2, 1, 125);
    RUN(8, 1, 2, 2, 170);
    RUN(9, 1, 2, 3, 245);
#pragma unroll
    for (int j = 0; j < 4; j++)
        if (vj[j])
#pragma unroll
            for (int o = 0; o < 3; o++)
                atomicAdd(&out[(size_t)aj[j] * FEAT + 16 + m * 3 + o],
                          nn[j] * outv[j][o]);
#pragma unroll
    for (int j = 0; j < 4; j++)
#pragma unroll
        for (int o = 0; o < 5; o++) outv[j][o] = 0.f;

    // ---------------- io = 2 (DOUT = 5, out offset 64) ----------------------
    RUN(10, 2, 0, 2, 350);
    RUN(11, 2, 1, 1, 375);
    RUN(12, 2, 1, 2, 420);
    RUN(13, 2, 1, 3, 495);
    RUN(14, 2, 2, 0, 600);
    RUN(15, 2, 2, 1, 625);
    RUN(16, 2, 2, 2, 700);
    RUN(17, 2, 2, 3, 825);
    RUN(18, 2, 2, 4, 1000);
#pragma unroll
    for (int j = 0; j < 4; j++)
        if (vj[j])
#pragma unroll
            for (int o = 0; o < 5; o++)
                atomicAdd(&out[(size_t)aj[j] * FEAT + 64 + m * 5 + o],
                          nn[j] * outv[j][o]);

#undef RUN
#undef STAGE_R
}

// ---------------------------------------------------------------------------
extern "C" void kernel_launch(void* const* d_in, const int* in_sizes, int n_in,
                              void* d_out, int out_size)
{
    const float* features = (const float*)d_in[0];
    const float* R        = (const float*)d_in[1];
    const float* Ys       = (const float*)d_in[2];
    const float* radii    = (const float*)d_in[3];
    const float* cg       = (const float*)d_in[4];
    const float* n_norm   = (const float*)d_in[5];
    const int*   map_a    = (const int*)d_in[6];
    const int*   map_b    = (const int*)d_in[7];
    float*       out      = (float*)d_out;

    cudaMemcpyToSymbolAsync(cg_c, cg, 1225 * sizeof(float), 0,
                            cudaMemcpyDeviceToDevice, 0);
    cudaMemsetAsync(out, 0, (size_t)out_size * sizeof(float));

    int grid = (N_EDGES + TILE_E - 1) / TILE_E;   // 7813
    conv_kernel<<<grid, THREADS>>>(features, R, Ys, radii, n_norm,
                                   map_a, map_b, out);
}

// round 3
// speedup vs baseline: 1.8991x; 1.8991x over previous
#include <cuda_runtime.h>

#define N_EDGES 250000
#define N_RBF   10
#define FEAT    144
#define P_TOTAL 4864
#define TILE_E  32
#define THREADS 256
#define VSTRIDE 20                      // w-row stride in floats (16 used + 4 pad)
#define RBUF    (N_RBF * 16 * VSTRIDE)  // 3200 floats per buffer

__constant__ float cg_c[1225];

// ---------------------------------------------------------------------------
// One path, fully unrolled. 2 edges per lane (A,B), lane m = mul index.
// tmp[v=m][o] lives in lane v's registers; apply fetches it via shfl(width16).
// Rt layout: [r][w][v] with w-row stride VSTRIDE -> lane w reads its own row
// as float4 (LDS.128), each value feeding 2 edges' W accumulation.
// ---------------------------------------------------------------------------
template<int IO, int II, int LF, int CGOFF>
__device__ __forceinline__ void do_path(
    const float* __restrict__ F_s,    // [TILE_E][FEAT]
    const float* __restrict__ Ys_s,   // [TILE_E][25]
    const float* __restrict__ Rt,     // [10][16][VSTRIDE]
    const float (&radA)[N_RBF], const float (&radB)[N_RBF],
    int m, int lA, int lB,
    float (&outA)[5], float (&outB)[5])
{
    constexpr int DOUT = 2 * IO + 1;
    constexpr int DI   = 2 * II + 1;
    constexpr int DF   = 2 * LF + 1;
    constexpr int FOFF = (II == 0) ? 0 : ((II == 1) ? 16 : 64);
    constexpr int YOFF = LF * LF;
    const float NORM =
        (DF == 1) ? 1.0f :
        (DF == 3) ? 0.57735026918962576f :
        (DF == 5) ? 0.44721359549995794f :
        (DF == 7) ? 0.37796447300922723f :
                    0.33333333333333333f;

    // ---- tmp[v=m][o] for both edges ----
    float FA[DI], FB[DI];
#pragma unroll
    for (int i = 0; i < DI; i++) {
        FA[i] = F_s[lA * FEAT + FOFF + m * DI + i];
        FB[i] = F_s[lB * FEAT + FOFF + m * DI + i];
    }
    float tA[DOUT], tB[DOUT];
#pragma unroll
    for (int o = 0; o < DOUT; o++) { tA[o] = 0.f; tB[o] = 0.f; }

#pragma unroll
    for (int f = 0; f < DF; f++) {
        float yA = Ys_s[lA * 25 + YOFF + f];
        float yB = Ys_s[lB * 25 + YOFF + f];
#pragma unroll
        for (int o = 0; o < DOUT; o++) {
            float gA = 0.f, gB = 0.f;
#pragma unroll
            for (int i = 0; i < DI; i++) {
                float c = cg_c[CGOFF + (o * DI + i) * DF + f];  // LDCU, uniform port
                gA += FA[i] * c;
                gB += FB[i] * c;
            }
            tA[o] += yA * gA;
            tB[o] += yB * gB;
        }
    }
#pragma unroll
    for (int o = 0; o < DOUT; o++) { tA[o] *= NORM; tB[o] *= NORM; }

    // ---- W[w=m][v] via LDS.128 over v-groups + apply via shfl ----
    const float* row = Rt + m * VSTRIDE;
#pragma unroll
    for (int vg = 0; vg < 4; vg++) {
        float wA[4] = {0.f, 0.f, 0.f, 0.f};
        float wB[4] = {0.f, 0.f, 0.f, 0.f};
#pragma unroll
        for (int r = 0; r < N_RBF; r++) {
            float4 q = *(const float4*)(row + r * (16 * VSTRIDE) + vg * 4);
            wA[0] += radA[r] * q.x;  wB[0] += radB[r] * q.x;
            wA[1] += radA[r] * q.y;  wB[1] += radB[r] * q.y;
            wA[2] += radA[r] * q.z;  wB[2] += radB[r] * q.z;
            wA[3] += radA[r] * q.w;  wB[3] += radB[r] * q.w;
        }
#pragma unroll
        for (int k = 0; k < 4; k++) {
            const int v = vg * 4 + k;
#pragma unroll
            for (int o = 0; o < DOUT; o++) {
                float tvA = __shfl_sync(0xffffffffu, tA[o], v, 16);
                float tvB = __shfl_sync(0xffffffffu, tB[o], v, 16);
                outA[o] += wA[k] * tvA;
                outB[o] += wB[k] * tvB;
            }
        }
    }
}

// ---------------------------------------------------------------------------
__global__ void __launch_bounds__(THREADS, 2)
conv_kernel(const float* __restrict__ features,
            const float* __restrict__ R,
            const float* __restrict__ Ys,
            const float* __restrict__ radii,
            const float* __restrict__ n_norm,
            const int*   __restrict__ map_a,
            const int*   __restrict__ map_b,
            float* __restrict__ out)
{
    __shared__ __align__(16) float Rt[2][RBUF];       // double-buffered R, [r][w][v]
    __shared__ __align__(16) float F_s[TILE_E * FEAT];
    __shared__ float Ys_s[TILE_E * 25];

    const int tid  = threadIdx.x;
    const int warp = tid >> 5;
    const int lane = tid & 31;
    const int m    = lane & 15;
    const int eh   = lane >> 4;
    const int e0   = blockIdx.x * TILE_E;
    const int lA   = warp * 4 + eh * 2;
    const int lB   = lA + 1;

    // prefetch registers: with 256 threads, idx = k*256+tid -> r = k, c = tid
    const int pw = tid >> 4;          // w index of this thread's R column
    const int pv = tid & 15;          // v index
    float pf[N_RBF];

#define PREFETCH(P)                                                            \
    do {                                                                       \
        _Pragma("unroll")                                                      \
        for (int k = 0; k < N_RBF; k++)                                        \
            pf[k] = R[(size_t)k * P_TOTAL + (P) * 256 + tid];                  \
    } while (0)

#define COMMIT(BUF)                                                            \
    do {                                                                       \
        _Pragma("unroll")                                                      \
        for (int k = 0; k < N_RBF; k++)                                        \
            Rt[(BUF)][(k * 16 + pw) * VSTRIDE + pv] = pf[k];                   \
    } while (0)

    // ---- prologue: R path0 -> buf0, prefetch path1; stage F/Ys meanwhile ----
    PREFETCH(0);

    {
        const int NV = TILE_E * FEAT / 4;   // 1152 float4
        for (int idx = tid; idx < NV; idx += THREADS) {
            int le = idx / (FEAT / 4), c4 = idx - le * (FEAT / 4);
            int e  = e0 + le;
            int b  = (e < N_EDGES) ? map_b[e] : 0;
            ((float4*)F_s)[idx] =
                ((const float4*)(features + (size_t)b * FEAT))[c4];
        }
    }
    for (int idx = tid; idx < TILE_E * 25; idx += THREADS) {
        int le = idx / 25, c = idx - le * 25;
        int e  = e0 + le;
        Ys_s[idx] = (e < N_EDGES) ? Ys[(size_t)e * 25 + c] : 0.f;
    }

    COMMIT(0);
    PREFETCH(1);

    // ---- per-lane edge bindings (2 edges) ----
    const int eA = e0 + lA, eB = e0 + lB;
    const bool vA = (eA < N_EDGES), vB = (eB < N_EDGES);
    const int eAc = vA ? eA : 0, eBc = vB ? eB : 0;

    float radA[N_RBF], radB[N_RBF];
#pragma unroll
    for (int r = 0; r < N_RBF; r++) {
        radA[r] = vA ? radii[(size_t)eAc * N_RBF + r] : 0.f;
        radB[r] = vB ? radii[(size_t)eBc * N_RBF + r] : 0.f;
    }
    const int   aA  = map_a[eAc];
    const int   aB  = map_a[eBc];
    const float nnA = vA ? n_norm[aA] : 0.f;
    const float nnB = vB ? n_norm[aB] : 0.f;

    float outA[5], outB[5];
#pragma unroll
    for (int o = 0; o < 5; o++) { outA[o] = 0.f; outB[o] = 0.f; }

    __syncthreads();   // F_s, Ys_s, Rt[0] visible

    // iteration P: commit pf (path P+1) -> buf[(P+1)&1]  (safe: last read in P-1,
    // synced), prefetch path P+2, compute path P from buf[P&1], sync.
#define STEP(P, IO, II, LF, CGOFF)                                             \
    do {                                                                       \
        if ((P) < 18) COMMIT(((P) + 1) & 1);                                   \
        if ((P) < 17) PREFETCH((P) + 2);                                       \
        do_path<IO, II, LF, CGOFF>(F_s, Ys_s, Rt[(P) & 1], radA, radB,         \
                                   m, lA, lB, outA, outB);                     \
        if ((P) < 18) __syncthreads();                                         \
    } while (0)

    // ---------------- io = 0 (DOUT = 1, out offset 0) -----------------------
    STEP(0, 0, 0, 0, 0);
    STEP(1, 0, 1, 1, 1);
    STEP(2, 0, 2, 2, 10);
    if (vA) atomicAdd(&out[(size_t)aA * FEAT + m], nnA * outA[0]);
    if (vB) atomicAdd(&out[(size_t)aB * FEAT + m], nnB * outB[0]);
#pragma unroll
    for (int o = 0; o < 5; o++) { outA[o] = 0.f; outB[o] = 0.f; }

    // ---------------- io = 1 (DOUT = 3, out offset 16) ----------------------
    STEP(3, 1, 0, 1, 35);
    STEP(4, 1, 1, 0, 44);
    STEP(5, 1, 1, 1, 53);
    STEP(6, 1, 1, 2, 80);
    STEP(7, 1, 2, 1, 125);
    STEP(8, 1, 2, 2, 170);
    STEP(9, 1, 2, 3, 245);
#pragma unroll
    for (int o = 0; o < 3; o++) {
        if (vA) atomicAdd(&out[(size_t)aA * FEAT + 16 + m * 3 + o], nnA * outA[o]);
        if (vB) atomicAdd(&out[(size_t)aB * FEAT + 16 + m * 3 + o], nnB * outB[o]);
    }
#pragma unroll
    for (int o = 0; o < 5; o++) { outA[o] = 0.f; outB[o] = 0.f; }

    // ---------------- io = 2 (DOUT = 5, out offset 64) ----------------------
    STEP(10, 2, 0, 2, 350);
    STEP(11, 2, 1, 1, 375);
    STEP(12, 2, 1, 2, 420);
    STEP(13, 2, 1, 3, 495);
    STEP(14, 2, 2, 0, 600);
    STEP(15, 2, 2, 1, 625);
    STEP(16, 2, 2, 2, 700);
    STEP(17, 2, 2, 3, 825);
    STEP(18, 2, 2, 4, 1000);
#pragma unroll
    for (int o = 0; o < 5; o++) {
        if (vA) atomicAdd(&out[(size_t)aA * FEAT + 64 + m * 5 + o], nnA * outA[o]);
        if (vB) atomicAdd(&out[(size_t)aB * FEAT + 64 + m * 5 + o], nnB * outB[o]);
    }

#undef STEP
#undef COMMIT
#undef PREFETCH
}

// ---------------------------------------------------------------------------
extern "C" void kernel_launch(void* const* d_in, const int* in_sizes, int n_in,
                              void* d_out, int out_size)
{
    const float* features = (const float*)d_in[0];
    const float* R        = (const float*)d_in[1];
    const float* Ys       = (const float*)d_in[2];
    const float* radii    = (const float*)d_in[3];
    const float* cg       = (const float*)d_in[4];
    const float* n_norm   = (const float*)d_in[5];
    const int*   map_a    = (const int*)d_in[6];
    const int*   map_b    = (const int*)d_in[7];
    float*       out      = (float*)d_out;

    cudaMemcpyToSymbolAsync(cg_c, cg, 1225 * sizeof(float), 0,
                            cudaMemcpyDeviceToDevice, 0);
    cudaMemsetAsync(out, 0, (size_t)out_size * sizeof(float));

    int grid = (N_EDGES + TILE_E - 1) / TILE_E;   // 7813
    conv_kernel<<<grid, THREADS>>>(features, R, Ys, radii, n_norm,
                                   map_a, map_b, out);
}

// round 4
// speedup vs baseline: 2.1615x; 1.1382x over previous
#include <cuda_runtime.h>

#define N_EDGES 250000
#define N_RBF   10
#define FEAT    144
#define P_TOTAL 4864
#define TILE_E  32
#define THREADS 256
#define VSTRIDE 20                      // Rt w-row stride (16 used + 4 pad)
#define RBUF    (N_RBF * 16 * VSTRIDE)  // 3200 floats per buffer
#define TMP_ESTR 84                     // tmp per-edge stride (5*16 + 4 pad, 16B mult)
#define TMP_WARP (4 * TMP_ESTR)         // 336 floats per warp

__constant__ float cg_c[1225];

// ---------------------------------------------------------------------------
// One path. 2 edges per lane (A,B); lane m = mul index (v in tmp phase, w in
// apply phase). tmp is exchanged through a per-warp smem scratch instead of
// shuffles: lane v writes tmp[le][o][v] (scalar STS, conflict-free), apply
// reads it back as broadcast LDS.128 over v-groups.
// ---------------------------------------------------------------------------
template<int IO, int II, int LF, int CGOFF>
__device__ __forceinline__ void do_path(
    const float (&FAr)[9], const float (&FBr)[9],   // per-lane feature slices
    const float* __restrict__ Ys_s,                 // [TILE_E][25]
    const float* __restrict__ Rt,                   // [10][16][VSTRIDE]
    float* __restrict__ tmp_w,                      // this warp's scratch
    const float (&radA)[N_RBF], const float (&radB)[N_RBF],
    int m, int lA, int lB, int leA,
    float (&outA)[5], float (&outB)[5])
{
    constexpr int DOUT = 2 * IO + 1;
    constexpr int DI   = 2 * II + 1;
    constexpr int DF   = 2 * LF + 1;
    constexpr int FB0  = (II == 0) ? 0 : ((II == 1) ? 1 : 4);
    constexpr int YOFF = LF * LF;
    const float NORM =
        (DF == 1) ? 1.0f :
        (DF == 3) ? 0.57735026918962576f :
        (DF == 5) ? 0.44721359549995794f :
        (DF == 7) ? 0.37796447300922723f :
                    0.33333333333333333f;

    // ---- tmp[v=m][o] for both edges (features from registers) ----
    float tA[DOUT], tB[DOUT];
#pragma unroll
    for (int o = 0; o < DOUT; o++) { tA[o] = 0.f; tB[o] = 0.f; }

#pragma unroll
    for (int f = 0; f < DF; f++) {
        float yA = Ys_s[lA * 25 + YOFF + f];
        float yB = Ys_s[lB * 25 + YOFF + f];
#pragma unroll
        for (int o = 0; o < DOUT; o++) {
            float gA = 0.f, gB = 0.f;
#pragma unroll
            for (int i = 0; i < DI; i++) {
                float c = cg_c[CGOFF + (o * DI + i) * DF + f];  // LDCU uniform
                gA += FAr[FB0 + i] * c;
                gB += FBr[FB0 + i] * c;
            }
            tA[o] += yA * gA;
            tB[o] += yB * gB;
        }
    }

    // ---- publish tmp to warp scratch ----
    __syncwarp();
#pragma unroll
    for (int o = 0; o < DOUT; o++) {
        tmp_w[ leA      * TMP_ESTR + o * 16 + m] = tA[o] * NORM;
        tmp_w[(leA + 1) * TMP_ESTR + o * 16 + m] = tB[o] * NORM;
    }
    __syncwarp();

    // ---- W[w=m][v] via LDS.128 + apply via broadcast LDS.128 over v ----
    const float* row = Rt + m * VSTRIDE;
#pragma unroll
    for (int vg = 0; vg < 4; vg++) {
        float wA[4] = {0.f, 0.f, 0.f, 0.f};
        float wB[4] = {0.f, 0.f, 0.f, 0.f};
#pragma unroll
        for (int r = 0; r < N_RBF; r++) {
            float4 q = *(const float4*)(row + r * (16 * VSTRIDE) + vg * 4);
            wA[0] += radA[r] * q.x;  wB[0] += radB[r] * q.x;
            wA[1] += radA[r] * q.y;  wB[1] += radB[r] * q.y;
            wA[2] += radA[r] * q.z;  wB[2] += radB[r] * q.z;
            wA[3] += radA[r] * q.w;  wB[3] += radB[r] * q.w;
        }
#pragma unroll
        for (int o = 0; o < DOUT; o++) {
            float4 qa = *(const float4*)(tmp_w +  leA      * TMP_ESTR + o * 16 + vg * 4);
            float4 qb = *(const float4*)(tmp_w + (leA + 1) * TMP_ESTR + o * 16 + vg * 4);
            outA[o] += wA[0] * qa.x + wA[1] * qa.y + wA[2] * qa.z + wA[3] * qa.w;
            outB[o] += wB[0] * qb.x + wB[1] * qb.y + wB[2] * qb.z + wB[3] * qb.w;
        }
    }
}

// ---------------------------------------------------------------------------
__global__ void __launch_bounds__(THREADS, 2)
conv_kernel(const float* __restrict__ features,
            const float* __restrict__ R,
            const float* __restrict__ Ys,
            const float* __restrict__ radii,
            const float* __restrict__ n_norm,
            const int*   __restrict__ map_a,
            const int*   __restrict__ map_b,
            float* __restrict__ out)
{
    __shared__ __align__(16) float Rt[2][RBUF];        // 25.6 kB
    __shared__ __align__(16) float tmp_s[8 * TMP_WARP];// 10.8 kB
    __shared__ float Ys_s[TILE_E * 25];                //  3.2 kB

    const int tid  = threadIdx.x;
    const int warp = tid >> 5;
    const int lane = tid & 31;
    const int m    = lane & 15;
    const int eh   = lane >> 4;
    const int e0   = blockIdx.x * TILE_E;
    const int leA  = eh * 2;               // local edge within warp scratch
    const int lA   = warp * 4 + leA;       // local edge within tile
    const int lB   = lA + 1;
    float* tmp_w   = tmp_s + warp * TMP_WARP;

    // R prefetch registers: idx = k*256+tid -> r = k, c = tid (c = w*16+v)
    const int pw = tid >> 4;
    const int pv = tid & 15;
    float pf[N_RBF];

#define PREFETCH(P)                                                            \
    do {                                                                       \
        _Pragma("unroll")                                                      \
        for (int k = 0; k < N_RBF; k++)                                        \
            pf[k] = R[(size_t)k * P_TOTAL + (P) * 256 + tid];                  \
    } while (0)

#define COMMIT(BUF)                                                            \
    do {                                                                       \
        _Pragma("unroll")                                                      \
        for (int k = 0; k < N_RBF; k++)                                        \
            Rt[(BUF)][(k * 16 + pw) * VSTRIDE + pv] = pf[k];                   \
    } while (0)

    PREFETCH(0);

    // ---- stage Ys ----
    for (int idx = tid; idx < TILE_E * 25; idx += THREADS) {
        int le = idx / 25, c = idx - le * 25;
        int e  = e0 + le;
        Ys_s[idx] = (e < N_EDGES) ? Ys[(size_t)e * 25 + c] : 0.f;
    }

    COMMIT(0);
    PREFETCH(1);

    // ---- per-lane bindings ----
    const int eA = e0 + lA, eB = e0 + lB;
    const bool vA = (eA < N_EDGES), vB = (eB < N_EDGES);
    const int eAc = vA ? eA : 0, eBc = vB ? eB : 0;

    // feature slices straight to registers (9 floats per edge)
    float FAr[9], FBr[9];
    {
        const float* fA = features + (size_t)map_b[eAc] * FEAT;
        const float* fB = features + (size_t)map_b[eBc] * FEAT;
        FAr[0] = fA[m];                 FBr[0] = fB[m];
#pragma unroll
        for (int i = 0; i < 3; i++) { FAr[1 + i] = fA[16 + m * 3 + i];
                                      FBr[1 + i] = fB[16 + m * 3 + i]; }
#pragma unroll
        for (int i = 0; i < 5; i++) { FAr[4 + i] = fA[64 + m * 5 + i];
                                      FBr[4 + i] = fB[64 + m * 5 + i]; }
    }

    float radA[N_RBF], radB[N_RBF];
#pragma unroll
    for (int r = 0; r < N_RBF; r++) {
        radA[r] = vA ? radii[(size_t)eAc * N_RBF + r] : 0.f;
        radB[r] = vB ? radii[(size_t)eBc * N_RBF + r] : 0.f;
    }
    const int   aA  = map_a[eAc];
    const int   aB  = map_a[eBc];
    const float nnA = vA ? n_norm[aA] : 0.f;
    const float nnB = vB ? n_norm[aB] : 0.f;

    float outA[5], outB[5];
#pragma unroll
    for (int o = 0; o < 5; o++) { outA[o] = 0.f; outB[o] = 0.f; }

    __syncthreads();   // Ys_s, Rt[0] visible

#define STEP(P, IO, II, LF, CGOFF)                                             \
    do {                                                                       \
        if ((P) < 18) COMMIT(((P) + 1) & 1);                                   \
        if ((P) < 17) PREFETCH((P) + 2);                                       \
        do_path<IO, II, LF, CGOFF>(FAr, FBr, Ys_s, Rt[(P) & 1], tmp_w,         \
                                   radA, radB, m, lA, lB, leA, outA, outB);    \
        if ((P) < 18) __syncthreads();                                         \
    } while (0)

    // ---------------- io = 0 (DOUT = 1, out offset 0) -----------------------
    STEP(0, 0, 0, 0, 0);
    STEP(1, 0, 1, 1, 1);
    STEP(2, 0, 2, 2, 10);
    if (vA) atomicAdd(&out[(size_t)aA * FEAT + m], nnA * outA[0]);
    if (vB) atomicAdd(&out[(size_t)aB * FEAT + m], nnB * outB[0]);
#pragma unroll
    for (int o = 0; o < 5; o++) { outA[o] = 0.f; outB[o] = 0.f; }

    // ---------------- io = 1 (DOUT = 3, out offset 16) ----------------------
    STEP(3, 1, 0, 1, 35);
    STEP(4, 1, 1, 0, 44);
    STEP(5, 1, 1, 1, 53);
    STEP(6, 1, 1, 2, 80);
    STEP(7, 1, 2, 1, 125);
    STEP(8, 1, 2, 2, 170);
    STEP(9, 1, 2, 3, 245);
#pragma unroll
    for (int o = 0; o < 3; o++) {
        if (vA) atomicAdd(&out[(size_t)aA * FEAT + 16 + m * 3 + o], nnA * outA[o]);
        if (vB) atomicAdd(&out[(size_t)aB * FEAT + 16 + m * 3 + o], nnB * outB[o]);
    }
#pragma unroll
    for (int o = 0; o < 5; o++) { outA[o] = 0.f; outB[o] = 0.f; }

    // ---------------- io = 2 (DOUT = 5, out offset 64) ----------------------
    STEP(10, 2, 0, 2, 350);
    STEP(11, 2, 1, 1, 375);
    STEP(12, 2, 1, 2, 420);
    STEP(13, 2, 1, 3, 495);
    STEP(14, 2, 2, 0, 600);
    STEP(15, 2, 2, 1, 625);
    STEP(16, 2, 2, 2, 700);
    STEP(17, 2, 2, 3, 825);
    STEP(18, 2, 2, 4, 1000);
#pragma unroll
    for (int o = 0; o < 5; o++) {
        if (vA) atomicAdd(&out[(size_t)aA * FEAT + 64 + m * 5 + o], nnA * outA[o]);
        if (vB) atomicAdd(&out[(size_t)aB * FEAT + 64 + m * 5 + o], nnB * outB[o]);
    }

#undef STEP
#undef COMMIT
#undef PREFETCH
}

// ---------------------------------------------------------------------------
extern "C" void kernel_launch(void* const* d_in, const int* in_sizes, int n_in,
                              void* d_out, int out_size)
{
    const float* features = (const float*)d_in[0];
    const float* R        = (const float*)d_in[1];
    const float* Ys       = (const float*)d_in[2];
    const float* radii    = (const float*)d_in[3];
    const float* cg       = (const float*)d_in[4];
    const float* n_norm   = (const float*)d_in[5];
    const int*   map_a    = (const int*)d_in[6];
    const int*   map_b    = (const int*)d_in[7];
    float*       out      = (float*)d_out;

    cudaMemcpyToSymbolAsync(cg_c, cg, 1225 * sizeof(float), 0,
                            cudaMemcpyDeviceToDevice, 0);
    cudaMemsetAsync(out, 0, (size_t)out_size * sizeof(float));

    int grid = (N_EDGES + TILE_E - 1) / TILE_E;   // 7813
    conv_kernel<<<grid, THREADS>>>(features, R, Ys, radii, n_norm,
                                   map_a, map_b, out);
}